// round 6
// baseline (speedup 1.0000x reference)
#include <cuda_runtime.h>
#include <cuda_fp16.h>
#include <math.h>

#define QTOT    16384          // 16 * 1024 rows
#define MM      2048           // 16 * 128 targets
#define KC      256
#define ROWS    16             // rows per block
#define THREADS 256

__device__ __forceinline__ float frcp(float x) {
    float r; asm("rcp.approx.ftz.f32 %0, %1;" : "=f"(r) : "f"(x)); return r;
}

// closed-form 1-D GIoU cost:
//   cb = |x0-t0| + |x1-t1|;  giou = (s-cb)/(s+cb), s = a1+a2;  C = 5cb - p - 2giou
__device__ __forceinline__ float elem(float x0, float x1, float a1,
                                      float t0, float t1, float a2, float p)
{
    const float cb  = fabsf(x0 - t0) + fabsf(x1 - t1);
    const float s   = a1 + a2;
    const float giou = (s - cb) * frcp(s + cb);
    return fmaf(-2.0f, giou, fmaf(5.0f, cb, -p));
}

__device__ __forceinline__ float sel2(const float2 v, int rr) {
    return rr == 0 ? v.x : v.y;
}

__global__ __launch_bounds__(THREADS, 5)
void matcher_kernel(const float* __restrict__ logits,   // [QTOT, KC]
                    const float* __restrict__ pboxes,   // [QTOT, 2] (mid, w)
                    const float* __restrict__ tboxes,   // [MM, 2]   (x0, x1)
                    const int*   __restrict__ tlabels,  // [MM]
                    float*       __restrict__ out)      // [QTOT, MM]
{
    // probH[id][r]: fp16 probs, 16 rows packed in 32B per class id
    __shared__ __align__(16) __half probH[KC * ROWS];   // 8 KB
    __shared__ float4 prow4[ROWS];                      // (x0, x1, a1, _)

    const int tid  = threadIdx.x;
    const int w    = tid >> 5, lane = tid & 31;
    const int rowbase = blockIdx.x * ROWS;

    // ---- pred boxes (mid,w) -> (x0,x1,area) ----
    if (tid < ROWS) {
        const float2 pb = reinterpret_cast<const float2*>(pboxes)[rowbase + tid];
        prow4[tid] = make_float4(pb.x - 0.5f * pb.y, pb.x + 0.5f * pb.y, pb.y, 0.0f);
    }

    // ---- softmax: warp w owns rows 2w and 2w+1 ----
    #pragma unroll
    for (int sub = 0; sub < 2; sub++) {
        const int r = 2 * w + sub;
        const float4* lrow = reinterpret_cast<const float4*>(
            logits + (size_t)(rowbase + r) * KC);
        float e[8];
        float sum = 0.0f;
        #pragma unroll
        for (int i = 0; i < 2; i++) {
            const float4 v = lrow[lane + 32 * i];            // LDG.128
            e[4*i+0] = __expf(v.x); e[4*i+1] = __expf(v.y);
            e[4*i+2] = __expf(v.z); e[4*i+3] = __expf(v.w);
            sum += e[4*i+0] + e[4*i+1] + e[4*i+2] + e[4*i+3];
        }
        #pragma unroll
        for (int o = 16; o; o >>= 1) sum += __shfl_xor_sync(0xffffffffu, sum, o);
        const float inv = frcp(sum);
        #pragma unroll
        for (int i = 0; i < 2; i++)
            #pragma unroll
            for (int c = 0; c < 4; c++) {
                const int id = 4 * (lane + 32 * i) + c;
                probH[id * ROWS + r] = __float2half(e[4*i+c] * inv);
            }
    }
    __syncthreads();

    const char* pbase = reinterpret_cast<const char*>(probH);

    // ---- main: 4 consecutive targets/thread x 2 groups, all 16 rows ----
    #pragma unroll 1
    for (int g = 0; g < 2; g++) {
        const int m = 4 * tid + 1024 * g;

        // direct LDG of this thread's 4 targets (L2-resident, no smem staging)
        const float4 B01 = reinterpret_cast<const float4*>(tboxes)[m / 2];      // t0,t1 of m,m+1
        const float4 B23 = reinterpret_cast<const float4*>(tboxes)[m / 2 + 1];  // t0,t1 of m+2,m+3
        const int4   L   = *reinterpret_cast<const int4*>(tlabels + m);

        const float t0x = B01.x, t1x = B01.y, t0y = B01.z, t1y = B01.w;
        const float t0z = B23.x, t1z = B23.y, t0w = B23.z, t1w = B23.w;
        const float a2x = t1x - t0x, a2y = t1y - t0y;
        const float a2z = t1z - t0z, a2w = t1w - t0w;
        const int o0 = L.x * (ROWS * 2), o1 = L.y * (ROWS * 2);
        const int o2 = L.z * (ROWS * 2), o3 = L.w * (ROWS * 2);

        float* ob = out + (size_t)rowbase * MM + m;

        #pragma unroll
        for (int h = 0; h < 2; h++) {       // row halves: rows 8h .. 8h+7
            // one LDS.128 per target = p for 8 rows (fp16 packed)
            const uint4 Q0 = *reinterpret_cast<const uint4*>(pbase + o0 + 16 * h);
            const uint4 Q1 = *reinterpret_cast<const uint4*>(pbase + o1 + 16 * h);
            const uint4 Q2 = *reinterpret_cast<const uint4*>(pbase + o2 + 16 * h);
            const uint4 Q3 = *reinterpret_cast<const uint4*>(pbase + o3 + 16 * h);

            #pragma unroll
            for (int j = 0; j < 4; j++) {   // row pair -> rows 8h+2j, 8h+2j+1
                const float2 p0 = __half22float2(reinterpret_cast<const __half2*>(&Q0)[j]);
                const float2 p1 = __half22float2(reinterpret_cast<const __half2*>(&Q1)[j]);
                const float2 p2 = __half22float2(reinterpret_cast<const __half2*>(&Q2)[j]);
                const float2 p3 = __half22float2(reinterpret_cast<const __half2*>(&Q3)[j]);
                #pragma unroll
                for (int rr = 0; rr < 2; rr++) {
                    const int r = 8 * h + 2 * j + rr;
                    const float4 pr = prow4[r];            // LDS.128 broadcast
                    const float x0 = pr.x, x1 = pr.y, a1 = pr.z;
                    float4 o;
                    o.x = elem(x0, x1, a1, t0x, t1x, a2x, sel2(p0, rr));
                    o.y = elem(x0, x1, a1, t0y, t1y, a2y, sel2(p1, rr));
                    o.z = elem(x0, x1, a1, t0z, t1z, a2z, sel2(p2, rr));
                    o.w = elem(x0, x1, a1, t0w, t1w, a2w, sel2(p3, rr));
                    __stcs(reinterpret_cast<float4*>(ob + (size_t)r * MM), o); // STG.128.CS
                }
            }
        }
    }
}

extern "C" void kernel_launch(void* const* d_in, const int* in_sizes, int n_in,
                              void* d_out, int out_size)
{
    const float* logits  = nullptr;   // 4194304
    const float* pboxes  = nullptr;   // 32768
    const float* tboxes  = nullptr;   // 4096
    const int*   tlabels = nullptr;   // 2048
    for (int i = 0; i < n_in; i++) {
        switch (in_sizes[i]) {
            case 4194304: logits  = (const float*)d_in[i]; break;
            case 32768:   pboxes  = (const float*)d_in[i]; break;
            case 4096:    tboxes  = (const float*)d_in[i]; break;
            case 2048:    tlabels = (const int*)d_in[i];   break;
            default: break;
        }
    }
    float* out = (float*)d_out;

    dim3 grid(QTOT / ROWS);     // 1024 blocks
    matcher_kernel<<<grid, THREADS>>>(logits, pboxes, tboxes, tlabels, out);
}

// round 7
// speedup vs baseline: 1.2008x; 1.2008x over previous
#include <cuda_runtime.h>
#include <cuda_fp16.h>
#include <math.h>

#define QTOT    16384          // 16 * 1024 rows
#define MM      2048           // 16 * 128 targets
#define KC      256
#define ROWS    8              // rows per block (16B/id gather stride — keep!)
#define THREADS 256

__device__ __forceinline__ float frcp(float x) {
    float r; asm("rcp.approx.ftz.f32 %0, %1;" : "=f"(r) : "f"(x)); return r;
}

// closed-form 1-D GIoU cost:
//   cb = |x0-t0| + |x1-t1|;  giou = (s-cb)/(s+cb), s = a1+a2;  C = 5cb - p - 2giou
__device__ __forceinline__ float elem(float x0, float x1, float a1,
                                      float t0, float t1, float a2, float p)
{
    const float cb  = fabsf(x0 - t0) + fabsf(x1 - t1);
    const float s   = a1 + a2;
    const float giou = (s - cb) * frcp(s + cb);
    return fmaf(-2.0f, giou, fmaf(5.0f, cb, -p));
}

__device__ __forceinline__ float sel2(const float2 v, int rr) {
    return rr == 0 ? v.x : v.y;
}

__global__ __launch_bounds__(THREADS, 5)
void matcher_kernel(const float* __restrict__ logits,   // [QTOT, KC]
                    const float* __restrict__ pboxes,   // [QTOT, 2] (mid, w)
                    const float* __restrict__ tboxes,   // [MM, 2]   (x0, x1)
                    const int*   __restrict__ tlabels,  // [MM]
                    float*       __restrict__ out)      // [QTOT, MM]
{
    // probH[id][r]: fp16 probs, 8 rows packed in 16B per class id
    __shared__ __align__(16) __half probH[KC * ROWS];   // 4 KB
    __shared__ float4 prow4[ROWS];                      // (x0, x1, a1, _)

    const int tid  = threadIdx.x;
    const int w    = tid >> 5, lane = tid & 31;
    const int rowbase = blockIdx.x * ROWS;

    // ---- pred boxes (mid,w) -> (x0,x1,area) ----
    if (tid < ROWS) {
        const float2 pb = reinterpret_cast<const float2*>(pboxes)[rowbase + tid];
        prow4[tid] = make_float4(pb.x - 0.5f * pb.y, pb.x + 0.5f * pb.y, pb.y, 0.0f);
    }

    // ---- softmax: warp w owns row w; packed fp16 prob table ----
    {
        const float4* lrow = reinterpret_cast<const float4*>(
            logits + (size_t)(rowbase + w) * KC);
        float e[8];
        float sum = 0.0f;
        #pragma unroll
        for (int i = 0; i < 2; i++) {
            const float4 v = lrow[lane + 32 * i];            // LDG.128
            e[4*i+0] = __expf(v.x); e[4*i+1] = __expf(v.y);
            e[4*i+2] = __expf(v.z); e[4*i+3] = __expf(v.w);
            sum += e[4*i+0] + e[4*i+1] + e[4*i+2] + e[4*i+3];
        }
        #pragma unroll
        for (int o = 16; o; o >>= 1) sum += __shfl_xor_sync(0xffffffffu, sum, o);
        const float inv = frcp(sum);
        #pragma unroll
        for (int i = 0; i < 2; i++)
            #pragma unroll
            for (int c = 0; c < 4; c++) {
                const int id = 4 * (lane + 32 * i) + c;
                probH[id * ROWS + w] = __float2half(e[4*i+c] * inv);
            }
    }
    __syncthreads();

    const char* pbase = reinterpret_cast<const char*>(probH);

    // ---- main: 4 consecutive targets/thread x 2 groups, all 8 rows ----
    #pragma unroll 1
    for (int g = 0; g < 2; g++) {
        const int m = 4 * tid + 1024 * g;

        // direct LDG of this thread's 4 targets (L2-resident, coalesced)
        const float4 B01 = reinterpret_cast<const float4*>(tboxes)[m / 2];      // t0,t1 of m,m+1
        const float4 B23 = reinterpret_cast<const float4*>(tboxes)[m / 2 + 1];  // t0,t1 of m+2,m+3
        const int4   L   = *reinterpret_cast<const int4*>(tlabels + m);

        const float t0x = B01.x, t1x = B01.y, t0y = B01.z, t1y = B01.w;
        const float t0z = B23.x, t1z = B23.y, t0w = B23.z, t1w = B23.w;
        const float a2x = t1x - t0x, a2y = t1y - t0y;
        const float a2z = t1z - t0z, a2w = t1w - t0w;

        // one LDS.128 per target = p for all 8 rows (fp16, 16B/id: 8-quad spread)
        const uint4 Q0 = *reinterpret_cast<const uint4*>(pbase + L.x * 16);
        const uint4 Q1 = *reinterpret_cast<const uint4*>(pbase + L.y * 16);
        const uint4 Q2 = *reinterpret_cast<const uint4*>(pbase + L.z * 16);
        const uint4 Q3 = *reinterpret_cast<const uint4*>(pbase + L.w * 16);

        float* ob = out + (size_t)rowbase * MM + m;

        #pragma unroll
        for (int j = 0; j < 4; j++) {      // row pair j -> rows 2j, 2j+1
            const float2 p0 = __half22float2(reinterpret_cast<const __half2*>(&Q0)[j]);
            const float2 p1 = __half22float2(reinterpret_cast<const __half2*>(&Q1)[j]);
            const float2 p2 = __half22float2(reinterpret_cast<const __half2*>(&Q2)[j]);
            const float2 p3 = __half22float2(reinterpret_cast<const __half2*>(&Q3)[j]);
            #pragma unroll
            for (int rr = 0; rr < 2; rr++) {
                const int r = 2 * j + rr;
                const float4 pr = prow4[r];               // LDS.128 broadcast
                const float x0 = pr.x, x1 = pr.y, a1 = pr.z;
                float4 o;
                o.x = elem(x0, x1, a1, t0x, t1x, a2x, sel2(p0, rr));
                o.y = elem(x0, x1, a1, t0y, t1y, a2y, sel2(p1, rr));
                o.z = elem(x0, x1, a1, t0z, t1z, a2z, sel2(p2, rr));
                o.w = elem(x0, x1, a1, t0w, t1w, a2w, sel2(p3, rr));
                __stcs(reinterpret_cast<float4*>(ob + (size_t)r * MM), o); // STG.128.CS
            }
        }
    }
}

extern "C" void kernel_launch(void* const* d_in, const int* in_sizes, int n_in,
                              void* d_out, int out_size)
{
    const float* logits  = nullptr;   // 4194304
    const float* pboxes  = nullptr;   // 32768
    const float* tboxes  = nullptr;   // 4096
    const int*   tlabels = nullptr;   // 2048
    for (int i = 0; i < n_in; i++) {
        switch (in_sizes[i]) {
            case 4194304: logits  = (const float*)d_in[i]; break;
            case 32768:   pboxes  = (const float*)d_in[i]; break;
            case 4096:    tboxes  = (const float*)d_in[i]; break;
            case 2048:    tlabels = (const int*)d_in[i];   break;
            default: break;
        }
    }
    float* out = (float*)d_out;

    dim3 grid(QTOT / ROWS);     // 2048 blocks
    matcher_kernel<<<grid, THREADS>>>(logits, pboxes, tboxes, tlabels, out);
}